// round 2
// baseline (speedup 1.0000x reference)
#include <cuda_runtime.h>
#include <math.h>

// ---------------- problem constants (fixed shapes) ----------------
#define Bb   112      // N*W = 2*56
#define NP   224      // NHH*Hh
#define PADN 19
#define EPSN 5e-5f

// ---------------- scratch (device globals; no allocs) --------------
__device__ float g_qkv[Bb * 5376];    // (b, o*56+h) flat == (b, t*96+f) view
__device__ int   g_undo[Bb * NP];
__device__ float g_wb [Bb * 9600];    // (b, u*2400 + t*32 + f)
__device__ float g_vb [Bb * 19200];   // (b, u*4800 + t*64 + f)
__device__ float g_ret[Bb * 38400];   // (b, g*4800 + u*1200 + k*400 + i*16 + e)
__device__ float g_bs [Bb * 2400];    // (b, g*300 + u*75 + k*25 + i)
__device__ float g_k4 [Bb * 19200];   // (b, u*4800 + jj*64 + o)
__device__ float g_bsn[Bb * 300];     // (b, u*75 + jj)

// ---------------- K1: qkv = conv_w @ x, + BN ----------------
__global__ void k1_qkv(const float* __restrict__ x, const float* __restrict__ cw,
                       const float* __restrict__ gamma, const float* __restrict__ beta) {
    __shared__ float xs[64 * 56];
    __shared__ float ws[48 * 64];
    int n = blockIdx.x / 56, h = blockIdx.x % 56;
    int o0 = blockIdx.y * 48;
    for (int idx = threadIdx.x; idx < 64 * 56; idx += blockDim.x) {
        int c = idx / 56, w = idx % 56;
        xs[idx] = x[((n * 64 + c) * 56 + h) * 56 + w];
    }
    for (int idx = threadIdx.x; idx < 48 * 64; idx += blockDim.x)
        ws[idx] = cw[o0 * 64 + idx];
    __syncthreads();
    const float invbn = rsqrtf(1.0f + 1e-5f);
    for (int idx = threadIdx.x; idx < 48 * 56; idx += blockDim.x) {
        int oo = idx / 56, w = idx % 56;
        int o = o0 + oo;
        float s = 0.f;
        #pragma unroll 16
        for (int c = 0; c < 64; c++) s += ws[oo * 64 + c] * xs[c * 56 + w];
        s = s * invbn * gamma[o] + beta[o];
        g_qkv[(n * 56 + w) * 5376 + o * 56 + h] = s;
    }
}

// ---------------- K2: LSH codes + stable argsort + gather/pad ----------------
__global__ void k2_sort(const float* __restrict__ rot) {
    __shared__ int code[NP];
    __shared__ int srcr[NP];
    int b = blockIdx.x;
    int tid = threadIdx.x;
    if (tid < NP) {
        int u = tid / 56, t = tid % 56;
        const float* q = &g_qkv[b * 5376 + t * 96];
        float s = 0.f;
        #pragma unroll 8
        for (int f = 0; f < 32; f++) s += q[f] * rot[f * 4 + u];
        code[tid] = (s < 0.f ? 1 : 0) + u * 2;   // argmax([r,-r]) + u*hash_buckets
    }
    __syncthreads();
    if (tid < NP) {
        int c = code[tid];
        int r = 0;
        for (int j = 0; j < NP; j++) {
            int cj = code[j];
            r += (cj < c) || (cj == c && j < tid);   // stable rank
        }
        g_undo[b * NP + tid] = r;
        srcr[r] = tid % 56;                           // mod = indices % H
    }
    __syncthreads();
    for (int idx = tid; idx < 9600; idx += blockDim.x) {
        int u = idx / 2400, r = idx % 2400, t = r / 32, f = r % 32;
        int tt = (t < 56) ? t : t - PADN;
        int row = srcr[u * 56 + tt];
        g_wb[b * 9600 + idx] = g_qkv[b * 5376 + row * 96 + f];
    }
    for (int idx = tid; idx < 19200; idx += blockDim.x) {
        int u = idx / 4800, r = idx % 4800, t = r / 64, f = r % 64;
        int tt = (t < 56) ? t : t - PADN;
        int row = srcr[u * 56 + tt];
        g_vb[b * 19200 + idx] = g_qkv[b * 5376 + row * 96 + 32 + f];
    }
}

// adjacency roll mapping: j in [0,75) at chunk k -> source t in [0,75)
__device__ __forceinline__ int src_t(int j, int k) {
    if (j < 25) return k * 25 + j;
    if (j < 50) return ((k + 2) % 3) * 25 + (j - 25);
    return ((k + 1) % 3) * 25 + (j - 50);
}

// ---------------- K3: fused scores / cross-group l2norm / softmax / V ----------------
__global__ __launch_bounds__(512, 2)
void k3_attn(const float* __restrict__ relative) {
    extern __shared__ float smf[];
    float* wr   = smf;            // 2400: raw w_b rows  [g][t][4]
    float* va   = wr + 2400;      // 4800: v_b rows      [g][t][8]
    float* we   = va + 4800;      // 300:  w_emb padded  [t][4]
    float* ve   = we + 300;       // 600:  v_emb padded  [t][8]
    float* winv = ve + 600;       // 600:  1/l2norm per row
    float* ss   = winv + 600;     // 15000: scores       [g][i][j]
    int*   stj  = (int*)(ss + 15000); // 75: roll table

    const int BD = 512;
    int blk = blockIdx.x;
    int b = blk / 12, r = blk % 12, u = r / 3, k = r % 3;
    int tid = threadIdx.x;

    const float* wbp = &g_wb[b * 9600 + u * 300];
    for (int idx = tid; idx < 2400; idx += BD)
        wr[idx] = wbp[(idx / 300) * 1200 + (idx % 300)];
    const float* vbp = &g_vb[b * 19200 + u * 600];
    for (int idx = tid; idx < 4800; idx += BD)
        va[idx] = vbp[(idx / 600) * 2400 + (idx % 600)];
    if (tid < 75) {
        int t = tid;
        int sr = (t < 56) ? t : t - PADN;
        #pragma unroll
        for (int e = 0; e < 4; e++) we[t * 4 + e] = relative[sr * 12 + e];
        #pragma unroll
        for (int e = 0; e < 8; e++) ve[t * 8 + e] = relative[sr * 12 + 4 + e];
        stj[t] = src_t(t, k);
    }
    __syncthreads();
    for (int rw = tid; rw < 600; rw += BD) {
        float4 p = *(const float4*)&wr[rw * 4];
        float s = p.x*p.x + p.y*p.y + p.z*p.z + p.w*p.w;
        winv[rw] = 1.0f / fmaxf(sqrtf(s), EPSN);
    }
    __syncthreads();

    // phase 1: scores for all (i,j), cross-group l2norm over 16 channels
    for (int pos = tid; pos < 1875; pos += BD) {
        int i = pos / 75, j = pos % 75;
        int ti = k * 25 + i;
        int tj = stj[j];
        float4 wej = *(const float4*)&we[tj * 4];
        float rawv[8], embv[8];
        float sq = 0.f;
        #pragma unroll
        for (int g = 0; g < 8; g++) {
            float4 a = *(const float4*)&wr[(g * 75 + ti) * 4];
            float4 m = *(const float4*)&wr[(g * 75 + tj) * 4];
            float iv = winv[g * 75 + tj];
            float rv = (a.x*m.x + a.y*m.y + a.z*m.z + a.w*m.w) * iv;
            float ev = 0.1f * (a.x*wej.x + a.y*wej.y + a.z*wej.z + a.w*wej.w);
            rawv[g] = rv; embv[g] = ev;
            sq += rv * rv + ev * ev;
        }
        float inv = 1.0f / fmaxf(sqrtf(sq), EPSN);
        #pragma unroll
        for (int g = 0; g < 8; g++)
            ss[g * 1875 + i * 75 + j] = (rawv[g] + embv[g]) * inv;
    }
    __syncthreads();

    // phase 2: each (g,i) row handled by a thread PAIR (lanes 2r, 2r+1)
    {
        int rowid = tid >> 1;
        int h = tid & 1;
        bool act = rowid < 200;
        int rr = act ? rowid : 199;       // clamp so all lanes run the shfls
        int g = rr / 25, i = rr % 25;
        const float* row = &ss[g * 1875 + i * 75];
        int j0 = h ? 38 : 0, j1 = h ? 75 : 38;
        float m = -1e30f;
        for (int j = j0; j < j1; j++) m = fmaxf(m, row[j]);
        m = fmaxf(m, __shfl_xor_sync(0xffffffffu, m, 1));
        float acc[16];
        #pragma unroll
        for (int e = 0; e < 16; e++) acc[e] = 0.f;
        float sum = 0.f;
        for (int j = j0; j < j1; j++) {
            float e0 = __expf(row[j] - m);
            sum += e0;
            int tj = stj[j];
            float4 v0 = *(const float4*)&va[(g * 75 + tj) * 8];
            float4 v1 = *(const float4*)&va[(g * 75 + tj) * 8 + 4];
            float4 w0 = *(const float4*)&ve[tj * 8];
            float4 w1 = *(const float4*)&ve[tj * 8 + 4];
            acc[0]  += e0 * v0.x; acc[1]  += e0 * v0.y; acc[2]  += e0 * v0.z; acc[3]  += e0 * v0.w;
            acc[4]  += e0 * v1.x; acc[5]  += e0 * v1.y; acc[6]  += e0 * v1.z; acc[7]  += e0 * v1.w;
            acc[8]  += e0 * w0.x; acc[9]  += e0 * w0.y; acc[10] += e0 * w0.z; acc[11] += e0 * w0.w;
            acc[12] += e0 * w1.x; acc[13] += e0 * w1.y; acc[14] += e0 * w1.z; acc[15] += e0 * w1.w;
        }
        sum += __shfl_xor_sync(0xffffffffu, sum, 1);
        #pragma unroll
        for (int e = 0; e < 16; e++) acc[e] += __shfl_xor_sync(0xffffffffu, acc[e], 1);
        if (act && h == 0) {
            float invs = 1.0f / sum;
            g_bs[b * 2400 + g * 300 + u * 75 + k * 25 + i] = m + __logf(sum);
            float* op = &g_ret[b * 38400 + g * 4800 + u * 1200 + k * 400 + i * 16];
            #pragma unroll
            for (int e = 0; e < 8; e++) {
                op[e]     = acc[e] * invs;            // F_GV2 = 1.0
                op[8 + e] = 0.1f * acc[8 + e] * invs; // F_GV1 = 0.1
            }
        }
    }
}

// ---------------- K4: 128-channel l2norm + pair-sum; bs group-norm ----------------
__global__ void k4_norm() {
    __shared__ float nrm[300];
    int b = blockIdx.x;
    int tid = threadIdx.x;
    for (int m = tid; m < 300; m += blockDim.x) nrm[m] = 0.f;
    __syncthreads();
    // coalesced streaming pass; bin v^2 by m = L % 300 via shared atomics
    {
        const float* p = &g_ret[b * 38400];
        int m = tid % 300;                 // blockDim = 512; 512 mod 300 = 212
        for (int L = tid; L < 38400; L += 512) {
            float v = p[L];
            atomicAdd(&nrm[m], v * v);
            m += 212; if (m >= 300) m -= 300;
        }
    }
    __syncthreads();
    for (int m = tid; m < 300; m += blockDim.x)
        nrm[m] = fmaxf(sqrtf(nrm[m]), EPSN);
    for (int m = tid; m < 300; m += blockDim.x) {
        const float* p = &g_bs[b * 2400 + m];
        float vals[8], s = 0.f;
        #pragma unroll
        for (int g = 0; g < 8; g++) { vals[g] = p[g * 300]; s += vals[g] * vals[g]; }
        float inv = 1.0f / fmaxf(sqrtf(s), EPSN);
        float t = 0.f;
        #pragma unroll
        for (int g = 0; g < 8; g++) t += vals[g] * inv;
        g_bsn[b * 300 + m] = t;
    }
    __syncthreads();
    for (int L2 = tid; L2 < 19200; L2 += blockDim.x) {
        int u = L2 / 4800, r = L2 % 4800, kk = r / 1600, r2 = r % 1600, i = r2 / 64, o = r2 % 64;
        int L0 = u * 9600 + kk * 3200 + i * 128 + o * 2;
        float x0 = g_ret[b * 38400 + L0];
        float x1 = g_ret[b * 38400 + L0 + 1];
        g_k4[b * 19200 + L2] = x0 / nrm[L0 % 300] + x1 / nrm[(L0 + 1) % 300];
    }
}

// ---------------- K5: unsort + hash softmax + output transpose ----------------
__global__ void k5_out(float* __restrict__ out) {
    __shared__ int   undo_s[NP];
    __shared__ float prob[4 * 56];
    __shared__ int   qoff[4 * 56];
    int b = blockIdx.x;
    int n = b / 56, w = b % 56;
    int tid = threadIdx.x;
    for (int j = tid; j < NP; j += blockDim.x) undo_s[j] = g_undo[b * NP + j];
    __syncthreads();
    if (tid < 56) {
        int h = tid;
        float bv[4];
        float mx = -1e30f;
        #pragma unroll
        for (int u = 0; u < 4; u++) {
            int q = undo_s[u * 56 + h];
            int qu = q / 56, qj = q % 56;
            bv[u] = g_bsn[b * 300 + qu * 75 + qj];
            qoff[u * 56 + h] = qu * 4800 + qj * 64;
            mx = fmaxf(mx, bv[u]);
        }
        float sm = 0.f;
        #pragma unroll
        for (int u = 0; u < 4; u++) { bv[u] = __expf(bv[u] - mx); sm += bv[u]; }
        #pragma unroll
        for (int u = 0; u < 4; u++) prob[u * 56 + h] = bv[u] / sm;
    }
    __syncthreads();
    for (int idx = tid; idx < 56 * 64; idx += blockDim.x) {
        int h = idx / 64, o = idx % 64;
        float acc = 0.f;
        #pragma unroll
        for (int u = 0; u < 4; u++)
            acc += prob[u * 56 + h] * g_k4[b * 19200 + qoff[u * 56 + h] + o];
        out[((n * 64 + o) * 56 + h) * 56 + w] = acc;
    }
}

// ---------------- launch ----------------
extern "C" void kernel_launch(void* const* d_in, const int* in_sizes, int n_in,
                              void* d_out, int out_size) {
    const float* x        = (const float*)d_in[0];
    const float* cw       = (const float*)d_in[1];
    const float* gamma    = (const float*)d_in[2];
    const float* beta     = (const float*)d_in[3];
    const float* relative = (const float*)d_in[4];
    const float* rotations= (const float*)d_in[5];
    float* out = (float*)d_out;

    cudaFuncSetAttribute(k3_attn, cudaFuncAttributeMaxDynamicSharedMemorySize, 95200);

    dim3 g1(112, 2);
    k1_qkv <<<g1, 256>>>(x, cw, gamma, beta);
    k2_sort<<<112, 256>>>(rotations);
    k3_attn<<<Bb * 12, 512, 95200>>>(relative);
    k4_norm<<<112, 512>>>();
    k5_out <<<112, 256>>>(out);
}

// round 3
// speedup vs baseline: 1.2019x; 1.2019x over previous
#include <cuda_runtime.h>
#include <math.h>

// ---------------- problem constants (fixed shapes) ----------------
#define Bb   112      // N*W = 2*56
#define NP   224      // NHH*Hh
#define PADN 19
#define EPSN 5e-5f

// ---------------- scratch (device globals; no allocs) --------------
__device__ float g_qkv[Bb * 5376];    // (b, o*56+h) flat == (b, t*96+f) view
__device__ int   g_undo[Bb * NP];
__device__ float g_wb [Bb * 9600];    // (b, u*2400 + t*32 + f)
__device__ float g_vb [Bb * 19200];   // (b, u*4800 + t*64 + f)
__device__ float g_ret[Bb * 38400];   // (b, g*4800 + u*1200 + k*400 + i*16 + e)
__device__ float g_bs [Bb * 2400];    // (b, g*300 + u*75 + k*25 + i)
__device__ float g_pn [Bb * 4 * 300]; // partial sum-of-squares per 32-channel slab

// ---------------- K1: qkv = conv_w @ x, + BN ----------------
__global__ void k1_qkv(const float* __restrict__ x, const float* __restrict__ cw,
                       const float* __restrict__ gamma, const float* __restrict__ beta) {
    __shared__ float xs[64 * 56];
    __shared__ float ws[48 * 64];
    int n = blockIdx.x / 56, h = blockIdx.x % 56;
    int o0 = blockIdx.y * 48;
    for (int idx = threadIdx.x; idx < 64 * 56; idx += blockDim.x) {
        int c = idx / 56, w = idx % 56;
        xs[idx] = x[((n * 64 + c) * 56 + h) * 56 + w];
    }
    for (int idx = threadIdx.x; idx < 48 * 64; idx += blockDim.x)
        ws[idx] = cw[o0 * 64 + idx];
    __syncthreads();
    const float invbn = rsqrtf(1.0f + 1e-5f);
    for (int idx = threadIdx.x; idx < 48 * 56; idx += blockDim.x) {
        int oo = idx / 56, w = idx % 56;
        int o = o0 + oo;
        float s = 0.f;
        #pragma unroll 16
        for (int c = 0; c < 64; c++) s += ws[oo * 64 + c] * xs[c * 56 + w];
        s = s * invbn * gamma[o] + beta[o];
        g_qkv[(n * 56 + w) * 5376 + o * 56 + h] = s;
    }
}

// ---------------- K2: LSH codes + stable argsort + gather/pad ----------------
__global__ void k2_sort(const float* __restrict__ rot) {
    __shared__ int code[NP];
    __shared__ int srcr[NP];
    int b = blockIdx.x;
    int tid = threadIdx.x;
    if (tid < NP) {
        int u = tid / 56, t = tid % 56;
        const float* q = &g_qkv[b * 5376 + t * 96];
        float s = 0.f;
        #pragma unroll 8
        for (int f = 0; f < 32; f++) s += q[f] * rot[f * 4 + u];
        code[tid] = (s < 0.f ? 1 : 0) + u * 2;   // argmax([r,-r]) + u*hash_buckets
    }
    __syncthreads();
    if (tid < NP) {
        int c = code[tid];
        int r = 0;
        for (int j = 0; j < NP; j++) {
            int cj = code[j];
            r += (cj < c) || (cj == c && j < tid);   // stable rank
        }
        g_undo[b * NP + tid] = r;
        srcr[r] = tid % 56;                           // mod = indices % H
    }
    __syncthreads();
    for (int idx = tid; idx < 9600; idx += blockDim.x) {
        int u = idx / 2400, r = idx % 2400, t = r / 32, f = r % 32;
        int tt = (t < 56) ? t : t - PADN;
        int row = srcr[u * 56 + tt];
        g_wb[b * 9600 + idx] = g_qkv[b * 5376 + row * 96 + f];
    }
    for (int idx = tid; idx < 19200; idx += blockDim.x) {
        int u = idx / 4800, r = idx % 4800, t = r / 64, f = r % 64;
        int tt = (t < 56) ? t : t - PADN;
        int row = srcr[u * 56 + tt];
        g_vb[b * 19200 + idx] = g_qkv[b * 5376 + row * 96 + 32 + f];
    }
}

// adjacency roll mapping: j in [0,75) at chunk k -> source t in [0,75)
__device__ __forceinline__ int src_t(int j, int k) {
    if (j < 25) return k * 25 + j;
    if (j < 50) return ((k + 2) % 3) * 25 + (j - 25);
    return ((k + 1) % 3) * 25 + (j - 50);
}

// ---------------- K3: fused scores / cross-group l2norm / softmax / V ----------------
__global__ __launch_bounds__(512, 2)
void k3_attn(const float* __restrict__ relative) {
    extern __shared__ float smf[];
    float* wr   = smf;            // 2400: raw w_b rows   [g][t][4]
    float* wn   = wr + 2400;      // 2400: l2norm'd rows  [g][t][4]
    float* va   = wn + 2400;      // 4800: v_b rows       [g][t][8]
    float* we   = va + 4800;      // 300:  w_emb padded   [t][4]
    float* ve   = we + 300;       // 600:  v_emb padded   [t][8]
    float* ss   = ve + 600;       // 15000: scores        [g][i][j]
    int*   stj  = (int*)(ss + 15000); // 75: roll table

    const int BD = 512;
    int blk = blockIdx.x;
    int b = blk / 12, r = blk % 12, u = r / 3, k = r % 3;
    int tid = threadIdx.x;

    const float* wbp = &g_wb[b * 9600 + u * 300];
    for (int idx = tid; idx < 2400; idx += BD)
        wr[idx] = wbp[(idx / 300) * 1200 + (idx % 300)];
    const float* vbp = &g_vb[b * 19200 + u * 600];
    for (int idx = tid; idx < 4800; idx += BD)
        va[idx] = vbp[(idx / 600) * 2400 + (idx % 600)];
    if (tid < 75) {
        int t = tid;
        int sr = (t < 56) ? t : t - PADN;
        #pragma unroll
        for (int e = 0; e < 4; e++) we[t * 4 + e] = relative[sr * 12 + e];
        #pragma unroll
        for (int e = 0; e < 8; e++) ve[t * 8 + e] = relative[sr * 12 + 4 + e];
        stj[t] = src_t(t, k);
    }
    __syncthreads();
    for (int rw = tid; rw < 600; rw += BD) {
        float4 p = *(const float4*)&wr[rw * 4];
        float s = p.x*p.x + p.y*p.y + p.z*p.z + p.w*p.w;
        float inv = 1.0f / fmaxf(sqrtf(s), EPSN);
        float4 q; q.x = p.x*inv; q.y = p.y*inv; q.z = p.z*inv; q.w = p.w*inv;
        *(float4*)&wn[rw * 4] = q;
    }
    __syncthreads();

    // phase 1: scores for all (i,j), cross-group l2norm over 16 channels
    for (int pos = tid; pos < 1875; pos += BD) {
        int i = pos / 75, j = pos % 75;
        int ti = k * 25 + i;
        int tj = stj[j];
        float4 wej = *(const float4*)&we[tj * 4];
        float rawv[8], embv[8];
        float sq = 0.f;
        #pragma unroll
        for (int g = 0; g < 8; g++) {
            float4 a = *(const float4*)&wr[(g * 75 + ti) * 4];
            float4 m = *(const float4*)&wn[(g * 75 + tj) * 4];
            float rv = a.x*m.x + a.y*m.y + a.z*m.z + a.w*m.w;
            float ev = 0.1f * (a.x*wej.x + a.y*wej.y + a.z*wej.z + a.w*wej.w);
            rawv[g] = rv; embv[g] = ev;
            sq += rv * rv + ev * ev;
        }
        float inv = 1.0f / fmaxf(sqrtf(sq), EPSN);
        #pragma unroll
        for (int g = 0; g < 8; g++)
            ss[g * 1875 + i * 75 + j] = (rawv[g] + embv[g]) * inv;
    }
    __syncthreads();

    // phase 2: each (g,i) row handled by a thread PAIR (lanes 2r, 2r+1)
    {
        int rowid = tid >> 1;
        int h = tid & 1;
        bool act = rowid < 200;
        int rr = act ? rowid : 199;       // clamp so all lanes run the shfls
        int g = rr / 25, i = rr % 25;
        const float* row = &ss[g * 1875 + i * 75];
        int j0 = h ? 38 : 0, j1 = h ? 75 : 38;
        float m = -1e30f;
        for (int j = j0; j < j1; j++) m = fmaxf(m, row[j]);
        m = fmaxf(m, __shfl_xor_sync(0xffffffffu, m, 1));
        float acc[16];
        #pragma unroll
        for (int e = 0; e < 16; e++) acc[e] = 0.f;
        float sum = 0.f;
        for (int j = j0; j < j1; j++) {
            float e0 = __expf(row[j] - m);
            sum += e0;
            int tj = stj[j];
            float4 v0 = *(const float4*)&va[(g * 75 + tj) * 8];
            float4 v1 = *(const float4*)&va[(g * 75 + tj) * 8 + 4];
            float4 w0 = *(const float4*)&ve[tj * 8];
            float4 w1 = *(const float4*)&ve[tj * 8 + 4];
            acc[0]  += e0 * v0.x; acc[1]  += e0 * v0.y; acc[2]  += e0 * v0.z; acc[3]  += e0 * v0.w;
            acc[4]  += e0 * v1.x; acc[5]  += e0 * v1.y; acc[6]  += e0 * v1.z; acc[7]  += e0 * v1.w;
            acc[8]  += e0 * w0.x; acc[9]  += e0 * w0.y; acc[10] += e0 * w0.z; acc[11] += e0 * w0.w;
            acc[12] += e0 * w1.x; acc[13] += e0 * w1.y; acc[14] += e0 * w1.z; acc[15] += e0 * w1.w;
        }
        sum += __shfl_xor_sync(0xffffffffu, sum, 1);
        #pragma unroll
        for (int e = 0; e < 16; e++) acc[e] += __shfl_xor_sync(0xffffffffu, acc[e], 1);
        if (act && h == 0) {
            float invs = 1.0f / sum;
            g_bs[b * 2400 + g * 300 + u * 75 + k * 25 + i] = m + __logf(sum);
            float* op = &g_ret[b * 38400 + g * 4800 + u * 1200 + k * 400 + i * 16];
            #pragma unroll
            for (int e = 0; e < 8; e++) {
                op[e]     = acc[e] * invs;            // F_GV2 = 1.0
                op[8 + e] = 0.1f * acc[8 + e] * invs; // F_GV1 = 0.1
            }
        }
    }
}

// ---------------- K4a: partial 32-channel sum-of-squares (coalesced, no atomics) ----
__global__ __launch_bounds__(320)
void k4a_partial() {
    int b = blockIdx.x, q = blockIdx.y;
    int t = threadIdx.x;
    if (t >= 300) return;
    const float* p = &g_ret[b * 38400 + q * 32 * 300];
    float s = 0.f;
    #pragma unroll
    for (int c = 0; c < 32; c++) { float v = p[c * 300 + t]; s += v * v; }
    g_pn[(b * 4 + q) * 300 + t] = s;
}

// ---------------- K5: norms + bs-norm + unsort + hash softmax + output ----------------
__global__ __launch_bounds__(512)
void k5_out(float* __restrict__ out) {
    __shared__ float nrm[300];
    __shared__ float bsn[300];
    __shared__ int   undo_s[NP];
    __shared__ float prob[NP];
    __shared__ int   off_s[NP];
    __shared__ int   mb_s[NP];
    int b = blockIdx.x;
    int n = b / 56, w = b % 56;
    int tid = threadIdx.x;

    for (int m = tid; m < 300; m += 512) {
        const float* pp = &g_pn[b * 1200 + m];
        float s = pp[0] + pp[300] + pp[600] + pp[900];
        nrm[m] = fmaxf(sqrtf(s), EPSN);
    }
    for (int m = tid; m < 300; m += 512) {
        const float* p = &g_bs[b * 2400 + m];
        float vals[8], s = 0.f;
        #pragma unroll
        for (int g = 0; g < 8; g++) { vals[g] = p[g * 300]; s += vals[g] * vals[g]; }
        float inv = 1.0f / fmaxf(sqrtf(s), EPSN);
        float t = 0.f;
        #pragma unroll
        for (int g = 0; g < 8; g++) t += vals[g] * inv;
        bsn[m] = t;
    }
    for (int j = tid; j < NP; j += 512) undo_s[j] = g_undo[b * NP + j];
    __syncthreads();

    if (tid < 56) {
        int h = tid;
        float bv[4];
        float mx = -1e30f;
        #pragma unroll
        for (int u = 0; u < 4; u++) {
            int q = undo_s[u * 56 + h];
            int qu = q / 56, qj = q % 56;
            int kk = qj / 25, i = qj % 25;
            bv[u] = bsn[qu * 75 + qj];
            off_s[u * 56 + h] = qu * 9600 + kk * 3200 + i * 128;
            int mb = kk * 200 + i * 128; mb %= 300;
            mb_s[u * 56 + h] = mb;
            mx = fmaxf(mx, bv[u]);
        }
        float sm = 0.f;
        #pragma unroll
        for (int u = 0; u < 4; u++) { bv[u] = __expf(bv[u] - mx); sm += bv[u]; }
        #pragma unroll
        for (int u = 0; u < 4; u++) prob[u * 56 + h] = bv[u] / sm;
    }
    __syncthreads();

    const float* rp = &g_ret[b * 38400];
    for (int idx = tid; idx < 56 * 64; idx += 512) {
        int h = idx / 64, o = idx % 64;
        float acc = 0.f;
        #pragma unroll
        for (int u = 0; u < 4; u++) {
            int e = u * 56 + h;
            int L0 = off_s[e] + o * 2;
            int m0 = mb_s[e] + o * 2; if (m0 >= 300) m0 -= 300;
            int m1 = m0 + 1;          if (m1 >= 300) m1 = 0;
            float x0 = rp[L0];
            float x1 = rp[L0 + 1];
            acc += prob[e] * (x0 / nrm[m0] + x1 / nrm[m1]);
        }
        out[((n * 64 + o) * 56 + h) * 56 + w] = acc;
    }
}

// ---------------- launch ----------------
extern "C" void kernel_launch(void* const* d_in, const int* in_sizes, int n_in,
                              void* d_out, int out_size) {
    const float* x        = (const float*)d_in[0];
    const float* cw       = (const float*)d_in[1];
    const float* gamma    = (const float*)d_in[2];
    const float* beta     = (const float*)d_in[3];
    const float* relative = (const float*)d_in[4];
    const float* rotations= (const float*)d_in[5];
    float* out = (float*)d_out;

    cudaFuncSetAttribute(k3_attn, cudaFuncAttributeMaxDynamicSharedMemorySize, 102304);

    dim3 g1(112, 2);
    k1_qkv <<<g1, 256>>>(x, cw, gamma, beta);
    k2_sort<<<112, 256>>>(rotations);
    k3_attn<<<Bb * 12, 512, 102304>>>(relative);
    dim3 g4(112, 4);
    k4a_partial<<<g4, 320>>>();
    k5_out <<<112, 512>>>(out);
}